// round 4
// baseline (speedup 1.0000x reference)
#include <cuda_runtime.h>
#include <cstdint>

#define B_  4
#define T_  2048
#define DM_ 1024
#define H_  16
#define DH_ 64
#define BH_ (B_ * H_)

// Scratch (allocation-free rule: __device__ globals)
__device__ float g_Q[BH_ * T_ * DH_];   // [b,h,t,d]
__device__ float g_K[BH_ * T_ * DH_];   // [b,h,t,d]
__device__ float g_V[BH_ * T_ * DH_];   // [b,h,t,d]
__device__ float g_A[B_ * T_ * H_ * DH_]; // [b,t,h,d] (contiguous (8192,1024))

// ---------------------------------------------------------------------------
// Generic tiled SGEMM: C = A(MxK) @ B(KxN), 128x128 block tile, BK=8,
// 256 threads, 8x8 per-thread microtile (two 4-wide quadrants per axis).
// MODE 0: scatter into g_Q      (N=1024; col -> h*64+d)
// MODE 1: scatter into g_K/g_V  (N=2048; col -> h*128+r, r<64 => K else V)
// MODE 2: plain store + bias    (out = A@Wo + bo)
// ---------------------------------------------------------------------------
template <int MODE>
__global__ __launch_bounds__(256) void sgemm_k(
    const float* __restrict__ A, const float* __restrict__ Bm,
    const float* __restrict__ bias, float* __restrict__ Cout,
    int N, int K)
{
    __shared__ float As[8][132];   // transposed A tile, padded
    __shared__ float Bs[8][128];

    const int tid = threadIdx.x;
    const int tx = tid & 15, ty = tid >> 4;
    const int m0 = blockIdx.y * 128;
    const int n0 = blockIdx.x * 128;

    float c[8][8];
#pragma unroll
    for (int i = 0; i < 8; i++)
#pragma unroll
        for (int j = 0; j < 8; j++) c[i][j] = 0.f;

    const int a_r = tid >> 1, a_k4 = (tid & 1) * 4;
    const int b_k = tid >> 5, b_n4 = (tid & 31) * 4;

    for (int k0 = 0; k0 < K; k0 += 8) {
        float4 av = *(const float4*)(A + (size_t)(m0 + a_r) * K + k0 + a_k4);
        As[a_k4 + 0][a_r] = av.x;
        As[a_k4 + 1][a_r] = av.y;
        As[a_k4 + 2][a_r] = av.z;
        As[a_k4 + 3][a_r] = av.w;
        *(float4*)(&Bs[b_k][b_n4]) =
            *(const float4*)(Bm + (size_t)(k0 + b_k) * N + n0 + b_n4);
        __syncthreads();

#pragma unroll
        for (int kt = 0; kt < 8; kt++) {
            float a[8], bb[8];
            *(float4*)(a)     = *(float4*)(&As[kt][ty * 4]);
            *(float4*)(a + 4) = *(float4*)(&As[kt][64 + ty * 4]);
            *(float4*)(bb)     = *(float4*)(&Bs[kt][tx * 4]);
            *(float4*)(bb + 4) = *(float4*)(&Bs[kt][64 + tx * 4]);
#pragma unroll
            for (int i = 0; i < 8; i++)
#pragma unroll
                for (int j = 0; j < 8; j++) c[i][j] += a[i] * bb[j];
        }
        __syncthreads();
    }

    // Epilogue: two 4-wide column quadrants per row -> float4 stores.
#pragma unroll
    for (int i = 0; i < 8; i++) {
        int row = m0 + ((i < 4) ? (ty * 4 + i) : (64 + ty * 4 + i - 4));
        int b = row >> 11;          // row / T_
        int t = row & (T_ - 1);
#pragma unroll
        for (int jq = 0; jq < 2; jq++) {
            int col = n0 + jq * 64 + tx * 4;
            float4 v = make_float4(c[i][jq * 4 + 0], c[i][jq * 4 + 1],
                                   c[i][jq * 4 + 2], c[i][jq * 4 + 3]);
            if (MODE == 0) {
                int h = col >> 6, d = col & 63;
                *(float4*)(g_Q + (((size_t)(b * H_ + h) * T_ + t) * DH_ + d)) = v;
            } else if (MODE == 1) {
                int h = col >> 7, r = col & 127;
                size_t base = ((size_t)(b * H_ + h) * T_ + t) * DH_;
                if (r < 64) *(float4*)(g_K + base + r) = v;
                else        *(float4*)(g_V + base + (r - 64)) = v;
            } else {
                float4 bv = *(const float4*)(bias + col);
                v.x += bv.x; v.y += bv.y; v.z += bv.z; v.w += bv.w;
                *(float4*)(Cout + (size_t)row * DM_ + col) = v;
            }
        }
    }
}

// ---------------------------------------------------------------------------
// Flash attention, fp32. Block: 128 queries x all keys (tiles of 64).
// 256 threads, per-thread 8 rows x 4 cols microtile. Online softmax.
// Writes O in [b,t,h,d] layout.
// ---------------------------------------------------------------------------
#define AQ_PAD 132   // 128 rows + pad (16B-aligned rows)
#define AK_PAD 68    // 64 + pad

__global__ __launch_bounds__(256) void attn_kernel(
    const float* __restrict__ mask, float* __restrict__ Aout)
{
    extern __shared__ float sm[];
    float* Qt  = sm;                       // [64][AQ_PAD]  (d-major, r inner)
    float* Pt  = Qt + 64 * AQ_PAD;         // [64][AQ_PAD]  (key-major, r inner)
    float* Kt  = Pt + 64 * AQ_PAD;         // [64][AK_PAD]  (d-major, key inner)
    float* Vs  = Kt + 64 * AK_PAD;         // [64][AK_PAD]  (key-major, d inner)
    float* msk = Vs + 64 * AK_PAD;         // [64]

    const int qb  = blockIdx.x * 128;
    const int bh  = blockIdx.y;
    const int b   = bh / H_;
    const int h   = bh % H_;
    const int tid = threadIdx.x;
    const int tx  = tid & 15, ty = tid >> 4;
    const int r0  = ty * 8, c0 = tx * 4;

    const float* Qg = g_Q + (size_t)bh * T_ * DH_;
    const float* Kg = g_K + (size_t)bh * T_ * DH_;
    const float* Vg = g_V + (size_t)bh * T_ * DH_;

    // Load Q tile transposed: Qt[d][r]
    for (int i = tid; i < 128 * 16; i += 256) {
        int r = i >> 4, d4 = (i & 15) << 2;
        float4 v = *(const float4*)(Qg + (size_t)(qb + r) * DH_ + d4);
        Qt[(d4 + 0) * AQ_PAD + r] = v.x;
        Qt[(d4 + 1) * AQ_PAD + r] = v.y;
        Qt[(d4 + 2) * AQ_PAD + r] = v.z;
        Qt[(d4 + 3) * AQ_PAD + r] = v.w;
    }

    float m_i[8], l_i[8], o[8][4];
#pragma unroll
    for (int i = 0; i < 8; i++) {
        m_i[i] = -1e30f; l_i[i] = 0.f;
#pragma unroll
        for (int j = 0; j < 4; j++) o[i][j] = 0.f;
    }

    for (int kt = 0; kt < T_; kt += 64) {
        __syncthreads();  // protect Kt/Vs/Pt from previous iteration readers
        // Load K (transposed) and V (natural), plus mask slice
        for (int i = tid; i < 64 * 16; i += 256) {
            int r = i >> 4, d4 = (i & 15) << 2;
            float4 kv = *(const float4*)(Kg + (size_t)(kt + r) * DH_ + d4);
            Kt[(d4 + 0) * AK_PAD + r] = kv.x;
            Kt[(d4 + 1) * AK_PAD + r] = kv.y;
            Kt[(d4 + 2) * AK_PAD + r] = kv.z;
            Kt[(d4 + 3) * AK_PAD + r] = kv.w;
            *(float4*)(Vs + r * AK_PAD + d4) =
                *(const float4*)(Vg + (size_t)(kt + r) * DH_ + d4);
        }
        if (tid < 64) msk[tid] = mask[b * T_ + kt + tid];
        __syncthreads();

        // S = Q K^T  (8x4 per thread)
        float s[8][4];
#pragma unroll
        for (int i = 0; i < 8; i++)
#pragma unroll
            for (int j = 0; j < 4; j++) s[i][j] = 0.f;

        for (int d = 0; d < 64; d++) {
            float4 qa = *(float4*)(Qt + d * AQ_PAD + r0);
            float4 qc = *(float4*)(Qt + d * AQ_PAD + r0 + 4);
            float4 kf = *(float4*)(Kt + d * AK_PAD + c0);
            float q[8] = {qa.x, qa.y, qa.z, qa.w, qc.x, qc.y, qc.z, qc.w};
            float kk[4] = {kf.x, kf.y, kf.z, kf.w};
#pragma unroll
            for (int i = 0; i < 8; i++)
#pragma unroll
                for (int j = 0; j < 4; j++) s[i][j] += q[i] * kk[j];
        }

        // scale + mask
#pragma unroll
        for (int j = 0; j < 4; j++) {
            float mv = msk[c0 + j];
#pragma unroll
            for (int i = 0; i < 8; i++)
                s[i][j] = (mv == 0.f) ? -1e30f : s[i][j] * 0.125f;
        }

        // online softmax per row (16 lanes share a row group)
#pragma unroll
        for (int i = 0; i < 8; i++) {
            float mx = fmaxf(fmaxf(s[i][0], s[i][1]), fmaxf(s[i][2], s[i][3]));
#pragma unroll
            for (int off = 8; off; off >>= 1)
                mx = fmaxf(mx, __shfl_xor_sync(0xffffffffu, mx, off, 16));
            float mnew = fmaxf(m_i[i], mx);
            float alpha = __expf(m_i[i] - mnew);
            m_i[i] = mnew;
            float tsum = 0.f;
#pragma unroll
            for (int j = 0; j < 4; j++) {
                s[i][j] = __expf(s[i][j] - mnew);
                tsum += s[i][j];
            }
#pragma unroll
            for (int off = 8; off; off >>= 1)
                tsum += __shfl_xor_sync(0xffffffffu, tsum, off, 16);
            l_i[i] = l_i[i] * alpha + tsum;
#pragma unroll
            for (int j = 0; j < 4; j++) o[i][j] *= alpha;
        }

        // stash P transposed: Pt[key][row]
#pragma unroll
        for (int j = 0; j < 4; j++)
#pragma unroll
            for (int i = 0; i < 8; i++)
                Pt[(c0 + j) * AQ_PAD + (r0 + i)] = s[i][j];
        __syncthreads();

        // O += P @ V   (cols of O are head-dims, also 64-wide)
        for (int k = 0; k < 64; k++) {
            float4 pa = *(float4*)(Pt + k * AQ_PAD + r0);
            float4 pc = *(float4*)(Pt + k * AQ_PAD + r0 + 4);
            float4 vf = *(float4*)(Vs + k * AK_PAD + c0);
            float p[8] = {pa.x, pa.y, pa.z, pa.w, pc.x, pc.y, pc.z, pc.w};
            float vv[4] = {vf.x, vf.y, vf.z, vf.w};
#pragma unroll
            for (int i = 0; i < 8; i++)
#pragma unroll
                for (int j = 0; j < 4; j++) o[i][j] += p[i] * vv[j];
        }
    }

    // epilogue: normalize + write [b,t,h,d]
#pragma unroll
    for (int i = 0; i < 8; i++) {
        float inv = 1.f / l_i[i];
        int t = qb + r0 + i;
        float4 v = make_float4(o[i][0] * inv, o[i][1] * inv,
                               o[i][2] * inv, o[i][3] * inv);
        *(float4*)(Aout + (((size_t)(b * T_ + t) * H_ + h) * DH_ + c0)) = v;
    }
}

// ---------------------------------------------------------------------------
extern "C" void kernel_launch(void* const* d_in, const int* in_sizes, int n_in,
                              void* d_out, int out_size)
{
    const float* x1   = (const float*)d_in[0];
    const float* x2   = (const float*)d_in[1];
    const float* mask = (const float*)d_in[2];
    const float* Wq   = (const float*)d_in[3];
    const float* Wkv  = (const float*)d_in[4];
    const float* Wo   = (const float*)d_in[5];
    const float* bo   = (const float*)d_in[6];
    float* out = (float*)d_out;

    // Attention kernel needs ~100 KB dynamic smem.
    const int attn_smem = (64 * AQ_PAD * 2 + 64 * AK_PAD * 2 + 64) * (int)sizeof(float);
    cudaFuncSetAttribute(attn_kernel,
                         cudaFuncAttributeMaxDynamicSharedMemorySize, attn_smem);

    dim3 blk(256);
    // Q projection: (8192 x 1024) @ (1024 x 1024)
    sgemm_k<0><<<dim3(DM_ / 128, (B_ * T_) / 128), blk>>>(x1, Wq, nullptr, nullptr, DM_, DM_);
    // KV projection: (8192 x 1024) @ (1024 x 2048)
    sgemm_k<1><<<dim3((2 * DM_) / 128, (B_ * T_) / 128), blk>>>(x2, Wkv, nullptr, nullptr, 2 * DM_, DM_);
    // Attention
    float* gA;
    cudaGetSymbolAddress((void**)&gA, g_A);
    attn_kernel<<<dim3(T_ / 128, BH_), blk, attn_smem>>>(mask, gA);
    // Output projection: (8192 x 1024) @ (1024 x 1024) + bias
    sgemm_k<2><<<dim3(DM_ / 128, (B_ * T_) / 128), blk>>>(gA, Wo, bo, out, DM_, DM_);
}

// round 10
// speedup vs baseline: 1.4308x; 1.4308x over previous
#include <cuda_runtime.h>
#include <cstdint>

#define B_  4
#define T_  2048
#define DM_ 1024
#define H_  16
#define DH_ 64
#define BH_ (B_ * H_)

// ---------------- scratch (allocation-free rule: __device__ globals) -------
__device__ float g_Q[BH_ * T_ * DH_];     // [b,h,t,d]
__device__ float g_K[BH_ * T_ * DH_];     // [b,h,t,d]
__device__ float g_V[BH_ * T_ * DH_];     // [b,h,t,d]
__device__ float g_A[B_ * T_ * H_ * DH_]; // [b,t,h,d] (tf32-rounded)
__device__ float g_WqT[DM_ * DM_];        // [n][k], tf32-rounded
__device__ float g_WkvT[2 * DM_ * DM_];   // [n][k], tf32-rounded
__device__ float g_WoT[DM_ * DM_];        // [n][k], tf32-rounded
__device__ float g_X1r[B_ * T_ * DM_];    // tf32-rounded x1
__device__ float g_X2r[B_ * T_ * DM_];    // tf32-rounded x2

// ---------------- helpers --------------------------------------------------
__device__ __forceinline__ uint32_t smem_to_u32(const void* p) {
    uint32_t a;
    asm("{ .reg .u64 t; cvta.to.shared.u64 t, %1; cvt.u32.u64 %0, t; }"
        : "=r"(a) : "l"(p));
    return a;
}
__device__ __forceinline__ float tf32r(float x) {
    uint32_t u;
    asm("cvt.rna.tf32.f32 %0, %1;" : "=r"(u) : "f"(x));
    return __uint_as_float(u);
}
#define CP16(dst_u32, src) \
    asm volatile("cp.async.cg.shared.global [%0], [%1], 16;" \
        :: "r"(dst_u32), "l"(src) : "memory")
#define CP_COMMIT() asm volatile("cp.async.commit_group;" ::: "memory")
#define CP_WAIT0()  asm volatile("cp.async.wait_group 0;" ::: "memory")

__device__ __forceinline__ void mma_tf32(float c[4],
    uint32_t a0, uint32_t a1, uint32_t a2, uint32_t a3,
    uint32_t b0, uint32_t b1)
{
    asm volatile(
        "mma.sync.aligned.m16n8k8.row.col.f32.tf32.tf32.f32 "
        "{%0,%1,%2,%3}, {%4,%5,%6,%7}, {%8,%9}, {%0,%1,%2,%3};"
        : "+f"(c[0]), "+f"(c[1]), "+f"(c[2]), "+f"(c[3])
        : "r"(a0), "r"(a1), "r"(a2), "r"(a3), "r"(b0), "r"(b1));
}

// ---------------- tf32 round-copy ------------------------------------------
__global__ __launch_bounds__(256) void round_copy_k(
    const float4* __restrict__ src, float4* __restrict__ dst, int n4)
{
    int i = blockIdx.x * 256 + threadIdx.x;
    if (i < n4) {
        float4 v = src[i];
        v.x = tf32r(v.x); v.y = tf32r(v.y); v.z = tf32r(v.z); v.w = tf32r(v.w);
        dst[i] = v;
    }
}

// ---------------- weight transpose + tf32 round: dst[n][k] = src[k][n] -----
__global__ __launch_bounds__(256) void transpose_k(
    const float* __restrict__ src, float* __restrict__ dst, int rows, int cols)
{
    __shared__ float t[32][33];
    int bx = blockIdx.x * 32, by = blockIdx.y * 32;
#pragma unroll
    for (int i = 0; i < 32; i += 8)
        t[threadIdx.y + i][threadIdx.x] =
            src[(size_t)(by + threadIdx.y + i) * cols + bx + threadIdx.x];
    __syncthreads();
#pragma unroll
    for (int i = 0; i < 32; i += 8)
        dst[(size_t)(bx + threadIdx.y + i) * rows + by + threadIdx.x] =
            tf32r(t[threadIdx.x][threadIdx.y + i]);
}

// ---------------------------------------------------------------------------
// tf32 mma.sync GEMM: C(M,N) = A(M,K) @ Bt(N,K)^T, K=1024.
// 128x128 CTA tile, BK=32, 8 warps (2x4), warp tile 64x32.
// cp.async double-buffered smem, stride-36 padding (conflict-free frags).
// MODE 0: scatter g_Q;  MODE 1: scatter g_K/g_V;  MODE 2: +bias -> out
// ---------------------------------------------------------------------------
#define GK   1024
#define NIT  (GK / 32)
#define TSTR 36
#define TSF  (128 * TSTR)          // floats per operand tile

template <int MODE>
__global__ __launch_bounds__(256) void tgemm_k(
    const float* __restrict__ A, const float* __restrict__ Bt,
    const float* __restrict__ bias, float* __restrict__ Cout)
{
    extern __shared__ float sm[];
    const uint32_t sbase = smem_to_u32(sm);

    const int tid = threadIdx.x;
    const int wid = tid >> 5, lane = tid & 31;
    const int g = lane >> 2, tg = lane & 3;
    const int warp_m = wid >> 2, warp_n = wid & 3;
    const int m0 = blockIdx.y * 128, n0 = blockIdx.x * 128;

    const int lr = tid >> 3;          // 0..31 (row within 32-row group)
    const int lc = (tid & 7) * 4;     // 0,4,...,28 (k col, float4)
    const float* Ag = A  + (size_t)(m0 + lr) * GK + lc;
    const float* Bg = Bt + (size_t)(n0 + lr) * GK + lc;

    float acc[4][4][4];
#pragma unroll
    for (int i = 0; i < 4; i++)
#pragma unroll
        for (int j = 0; j < 4; j++)
#pragma unroll
            for (int q = 0; q < 4; q++) acc[i][j][q] = 0.f;

    // issue one BK=32 tile pair into buffer p
    auto issue = [&](int it, int p) {
        const float* a = Ag + it * 32;
        const float* b = Bg + it * 32;
        uint32_t sa = sbase + (uint32_t)(p * 2 * TSF) * 4u;
        uint32_t sb = sa + (uint32_t)TSF * 4u;
        uint32_t so = (uint32_t)(lr * TSTR + lc) * 4u;
#pragma unroll
        for (int r = 0; r < 4; r++) {
            CP16(sa + so + (uint32_t)(r * 32 * TSTR) * 4u, a + (size_t)r * 32 * GK);
            CP16(sb + so + (uint32_t)(r * 32 * TSTR) * 4u, b + (size_t)r * 32 * GK);
        }
        CP_COMMIT();
    };

    issue(0, 0);
    for (int it = 0; it < NIT; it++) {
        const int p = it & 1;
        CP_WAIT0();
        __syncthreads();
        if (it + 1 < NIT) issue(it + 1, p ^ 1);

        const float* As = sm + p * 2 * TSF;
        const float* Bs = As + TSF;
#pragma unroll
        for (int s = 0; s < 4; s++) {
            const int k = s * 8 + tg;
            uint32_t bf[4][2];
#pragma unroll
            for (int j = 0; j < 4; j++) {
                const int n = warp_n * 32 + j * 8 + g;
                bf[j][0] = __float_as_uint(Bs[n * TSTR + k]);
                bf[j][1] = __float_as_uint(Bs[n * TSTR + k + 4]);
            }
#pragma unroll
            for (int i = 0; i < 4; i++) {
                const int m = warp_m * 64 + i * 16 + g;
                uint32_t a0 = __float_as_uint(As[m * TSTR + k]);
                uint32_t a1 = __float_as_uint(As[(m + 8) * TSTR + k]);
                uint32_t a2 = __float_as_uint(As[m * TSTR + k + 4]);
                uint32_t a3 = __float_as_uint(As[(m + 8) * TSTR + k + 4]);
#pragma unroll
                for (int j = 0; j < 4; j++)
                    mma_tf32(acc[i][j], a0, a1, a2, a3, bf[j][0], bf[j][1]);
            }
        }
    }

    // epilogue: each thread owns float2 pairs at (row, 2*tg) per 16x8 frag
#pragma unroll
    for (int i = 0; i < 4; i++) {
        const int row0 = m0 + warp_m * 64 + i * 16 + g;
#pragma unroll
        for (int half = 0; half < 2; half++) {
            const int row = row0 + half * 8;
            const int b = row >> 11, t = row & (T_ - 1);
#pragma unroll
            for (int j = 0; j < 4; j++) {
                const int col = n0 + warp_n * 32 + j * 8 + tg * 2;
                float2 v = make_float2(acc[i][j][half * 2], acc[i][j][half * 2 + 1]);
                if (MODE == 0) {
                    int h = col >> 6, d = col & 63;
                    *(float2*)(g_Q + (((size_t)(b * H_ + h) * T_ + t) * DH_ + d)) = v;
                } else if (MODE == 1) {
                    int h = col >> 7, r = col & 127;
                    float* base = (r < 64) ? g_K : g_V;
                    int d = r & 63;
                    *(float2*)(base + (((size_t)(b * H_ + h) * T_ + t) * DH_ + d)) = v;
                } else {
                    float2 bv = *(const float2*)(bias + col);
                    v.x += bv.x; v.y += bv.y;
                    *(float2*)(Cout + (size_t)row * DM_ + col) = v;
                }
            }
        }
    }
}

// ---------------- flash attention, fp32 SIMT (R3, + tf32 round on output) --
#define AQ_PAD 132
#define AK_PAD 68

__global__ __launch_bounds__(256) void attn_kernel(
    const float* __restrict__ mask, float* __restrict__ Aout)
{
    extern __shared__ float smf[];
    float* Qt  = smf;
    float* Pt  = Qt + 64 * AQ_PAD;
    float* Kt  = Pt + 64 * AQ_PAD;
    float* Vs  = Kt + 64 * AK_PAD;
    float* msk = Vs + 64 * AK_PAD;

    const int qb  = blockIdx.x * 128;
    const int bh  = blockIdx.y;
    const int b   = bh / H_;
    const int h   = bh % H_;
    const int tid = threadIdx.x;
    const int tx  = tid & 15, ty = tid >> 4;
    const int r0  = ty * 8, c0 = tx * 4;

    const float* Qg = g_Q + (size_t)bh * T_ * DH_;
    const float* Kg = g_K + (size_t)bh * T_ * DH_;
    const float* Vg = g_V + (size_t)bh * T_ * DH_;

    for (int i = tid; i < 128 * 16; i += 256) {
        int r = i >> 4, d4 = (i & 15) << 2;
        float4 v = *(const float4*)(Qg + (size_t)(qb + r) * DH_ + d4);
        Qt[(d4 + 0) * AQ_PAD + r] = v.x;
        Qt[(d4 + 1) * AQ_PAD + r] = v.y;
        Qt[(d4 + 2) * AQ_PAD + r] = v.z;
        Qt[(d4 + 3) * AQ_PAD + r] = v.w;
    }

    float m_i[8], l_i[8], o[8][4];
#pragma unroll
    for (int i = 0; i < 8; i++) {
        m_i[i] = -1e30f; l_i[i] = 0.f;
#pragma unroll
        for (int j = 0; j < 4; j++) o[i][j] = 0.f;
    }

    for (int kt = 0; kt < T_; kt += 64) {
        __syncthreads();
        for (int i = tid; i < 64 * 16; i += 256) {
            int r = i >> 4, d4 = (i & 15) << 2;
            float4 kv = *(const float4*)(Kg + (size_t)(kt + r) * DH_ + d4);
            Kt[(d4 + 0) * AK_PAD + r] = kv.x;
            Kt[(d4 + 1) * AK_PAD + r] = kv.y;
            Kt[(d4 + 2) * AK_PAD + r] = kv.z;
            Kt[(d4 + 3) * AK_PAD + r] = kv.w;
            *(float4*)(Vs + r * AK_PAD + d4) =
                *(const float4*)(Vg + (size_t)(kt + r) * DH_ + d4);
        }
        if (tid < 64) msk[tid] = mask[b * T_ + kt + tid];
        __syncthreads();

        float s[8][4];
#pragma unroll
        for (int i = 0; i < 8; i++)
#pragma unroll
            for (int j = 0; j < 4; j++) s[i][j] = 0.f;

        for (int d = 0; d < 64; d++) {
            float4 qa = *(float4*)(Qt + d * AQ_PAD + r0);
            float4 qc = *(float4*)(Qt + d * AQ_PAD + r0 + 4);
            float4 kf = *(float4*)(Kt + d * AK_PAD + c0);
            float q[8] = {qa.x, qa.y, qa.z, qa.w, qc.x, qc.y, qc.z, qc.w};
            float kk[4] = {kf.x, kf.y, kf.z, kf.w};
#pragma unroll
            for (int i = 0; i < 8; i++)
#pragma unroll
                for (int j = 0; j < 4; j++) s[i][j] += q[i] * kk[j];
        }

#pragma unroll
        for (int j = 0; j < 4; j++) {
            float mv = msk[c0 + j];
#pragma unroll
            for (int i = 0; i < 8; i++)
                s[i][j] = (mv == 0.f) ? -1e30f : s[i][j] * 0.125f;
        }

#pragma unroll
        for (int i = 0; i < 8; i++) {
            float mx = fmaxf(fmaxf(s[i][0], s[i][1]), fmaxf(s[i][2], s[i][3]));
#pragma unroll
            for (int off = 8; off; off >>= 1)
                mx = fmaxf(mx, __shfl_xor_sync(0xffffffffu, mx, off, 16));
            float mnew = fmaxf(m_i[i], mx);
            float alpha = __expf(m_i[i] - mnew);
            m_i[i] = mnew;
            float tsum = 0.f;
#pragma unroll
            for (int j = 0; j < 4; j++) {
                s[i][j] = __expf(s[i][j] - mnew);
                tsum += s[i][j];
            }
#pragma unroll
            for (int off = 8; off; off >>= 1)
                tsum += __shfl_xor_sync(0xffffffffu, tsum, off, 16);
            l_i[i] = l_i[i] * alpha + tsum;
#pragma unroll
            for (int j = 0; j < 4; j++) o[i][j] *= alpha;
        }

#pragma unroll
        for (int j = 0; j < 4; j++)
#pragma unroll
            for (int i = 0; i < 8; i++)
                Pt[(c0 + j) * AQ_PAD + (r0 + i)] = s[i][j];
        __syncthreads();

        for (int k = 0; k < 64; k++) {
            float4 pa = *(float4*)(Pt + k * AQ_PAD + r0);
            float4 pc = *(float4*)(Pt + k * AQ_PAD + r0 + 4);
            float4 vf = *(float4*)(Vs + k * AK_PAD + c0);
            float p[8] = {pa.x, pa.y, pa.z, pa.w, pc.x, pc.y, pc.z, pc.w};
            float vv[4] = {vf.x, vf.y, vf.z, vf.w};
#pragma unroll
            for (int i = 0; i < 8; i++)
#pragma unroll
                for (int j = 0; j < 4; j++) o[i][j] += p[i] * vv[j];
        }
    }

#pragma unroll
    for (int i = 0; i < 8; i++) {
        float inv = 1.f / l_i[i];
        int t = qb + r0 + i;
        // tf32-round here: g_A is consumed as the A operand of the tf32 MMA
        float4 v = make_float4(tf32r(o[i][0] * inv), tf32r(o[i][1] * inv),
                               tf32r(o[i][2] * inv), tf32r(o[i][3] * inv));
        *(float4*)(Aout + (((size_t)(b * T_ + t) * H_ + h) * DH_ + c0)) = v;
    }
}

// ---------------------------------------------------------------------------
extern "C" void kernel_launch(void* const* d_in, const int* in_sizes, int n_in,
                              void* d_out, int out_size)
{
    const float* x1   = (const float*)d_in[0];
    const float* x2   = (const float*)d_in[1];
    const float* mask = (const float*)d_in[2];
    const float* Wq   = (const float*)d_in[3];
    const float* Wkv  = (const float*)d_in[4];
    const float* Wo   = (const float*)d_in[5];
    const float* bo   = (const float*)d_in[6];
    float* out = (float*)d_out;

    float *gA, *gWqT, *gWkvT, *gWoT, *gX1r, *gX2r;
    cudaGetSymbolAddress((void**)&gA, g_A);
    cudaGetSymbolAddress((void**)&gWqT, g_WqT);
    cudaGetSymbolAddress((void**)&gWkvT, g_WkvT);
    cudaGetSymbolAddress((void**)&gWoT, g_WoT);
    cudaGetSymbolAddress((void**)&gX1r, g_X1r);
    cudaGetSymbolAddress((void**)&gX2r, g_X2r);

    const int gemm_smem = 4 * TSF * 4;  // 73728 bytes (2 buffers x (A+B))
    cudaFuncSetAttribute(tgemm_k<0>, cudaFuncAttributeMaxDynamicSharedMemorySize, gemm_smem);
    cudaFuncSetAttribute(tgemm_k<1>, cudaFuncAttributeMaxDynamicSharedMemorySize, gemm_smem);
    cudaFuncSetAttribute(tgemm_k<2>, cudaFuncAttributeMaxDynamicSharedMemorySize, gemm_smem);
    const int attn_smem = (64 * AQ_PAD * 2 + 64 * AK_PAD * 2 + 64) * (int)sizeof(float);
    cudaFuncSetAttribute(attn_kernel, cudaFuncAttributeMaxDynamicSharedMemorySize, attn_smem);

    // prep: tf32-round activations, transpose+round weights
    const int nx4 = (B_ * T_ * DM_) / 4;
    round_copy_k<<<(nx4 + 255) / 256, 256>>>((const float4*)x1, (float4*)gX1r, nx4);
    round_copy_k<<<(nx4 + 255) / 256, 256>>>((const float4*)x2, (float4*)gX2r, nx4);
    dim3 tb(32, 8);
    transpose_k<<<dim3(DM_ / 32, DM_ / 32), tb>>>(Wq, gWqT, DM_, DM_);
    transpose_k<<<dim3(2 * DM_ / 32, DM_ / 32), tb>>>(Wkv, gWkvT, DM_, 2 * DM_);
    transpose_k<<<dim3(DM_ / 32, DM_ / 32), tb>>>(Wo, gWoT, DM_, DM_);

    // projections (tf32 mma.sync)
    tgemm_k<0><<<dim3(DM_ / 128, (B_ * T_) / 128), 256, gemm_smem>>>(gX1r, gWqT, nullptr, nullptr);
    tgemm_k<1><<<dim3(2 * DM_ / 128, (B_ * T_) / 128), 256, gemm_smem>>>(gX2r, gWkvT, nullptr, nullptr);

    // attention (fp32 SIMT)
    attn_kernel<<<dim3(T_ / 128, BH_), 256, attn_smem>>>(mask, gA);

    // output projection + bias
    tgemm_k<2><<<dim3(DM_ / 128, (B_ * T_) / 128), 256, gemm_smem>>>(gA, gWoT, bo, out);
}